// round 9
// baseline (speedup 1.0000x reference)
#include <cuda_runtime.h>

#define ALPHA 0.9048374180359595f   // exp(-1/10), rounds to same f32 as JAX
#define BT 12800                     // B*T = 128*100

// Layer-1 pooled conv output, layout [sample = b*100+t][256 = c*64+y*8+x]
__device__ float g_h1[BT * 256];

// ---------------------------------------------------------------------------
// Stage 1: DIRECT conv1(5x5,pad2) then avgpool4, exact f32, canonical order.
// One sample per block, 256 threads; thread = (c, py, px).
// ---------------------------------------------------------------------------
__global__ void __launch_bounds__(256) k_stage1(const float* __restrict__ x,
                                                const float* __restrict__ w1) {
    __shared__ float xp[2][36][36];   // 2592 floats, zero-padded borders
    __shared__ float w1s[200];        // [4][2][5][5] raw
    int tid = threadIdx.x;

    float* xpf = (float*)xp;
    for (int idx = tid; idx < 2592; idx += 256) xpf[idx] = 0.f;
    if (tid < 200) w1s[tid] = w1[tid];
    __syncthreads();

    const float* xg = x + (size_t)blockIdx.x * 2048;
#pragma unroll
    for (int k = 0; k < 8; k++) {
        int idx = tid + k * 256;                     // [0,2048)
        int ic = idx >> 10, r = (idx >> 5) & 31, cl = idx & 31;
        xp[ic][r + 2][cl + 2] = xg[idx];
    }
    __syncthreads();

    // thread -> (c, py, px); feature layout matches scan: f = c*64 + py*8 + px
    int c = tid >> 6, pos = tid & 63, py = pos >> 3, px = pos & 7;

    float cacc[16];
#pragma unroll
    for (int i = 0; i < 16; i++) cacc[i] = 0.f;

#pragma unroll
    for (int ic = 0; ic < 2; ic++) {
        // 8x8 input window for this pool block (padded rows 4py..4py+7)
        float win[8][8];
#pragma unroll
        for (int r = 0; r < 8; r++)
#pragma unroll
            for (int cl = 0; cl < 8; cl++)
                win[r][cl] = xp[ic][4 * py + r][4 * px + cl];

#pragma unroll
        for (int ky = 0; ky < 5; ky++)
#pragma unroll
            for (int kx = 0; kx < 5; kx++) {
                float w = w1s[(c * 2 + ic) * 25 + ky * 5 + kx];
#pragma unroll
                for (int j = 0; j < 4; j++)
#pragma unroll
                    for (int i = 0; i < 4; i++)
                        cacc[j * 4 + i] = fmaf(w, win[j + ky][i + kx], cacc[j * 4 + i]);
            }
    }
    // avgpool4: mean of the 16 conv pixels (exact /16)
    float s = 0.f;
#pragma unroll
    for (int i = 0; i < 16; i++) s += cacc[i];
    g_h1[(size_t)blockIdx.x * 256 + tid] = s * (1.0f / 16.0f);
}

// ---------------------------------------------------------------------------
// Stages 2-5 fused: per-batch temporal scan (block = one b, 256 threads).
//   layer-1 exp_leak+LIF (256 lanes) -> spike pad in smem ->
//   DIRECT conv2(3x3,pad1)+avgpool2 (128 lanes) -> layer-2 exp_leak+LIF ->
//   linear [2,128] reduced per step.
// ---------------------------------------------------------------------------
__global__ void __launch_bounds__(256) k_scan(const float* __restrict__ w2,
                                              const float* __restrict__ lin_w,
                                              float* __restrict__ out) {
    __shared__ float spad[4][10][10];   // zero-padded layer-1 spikes
    __shared__ float w2s[288];          // [8][4][3][3] raw
    __shared__ float red[8];
    int tid = threadIdx.x;
    int b = blockIdx.x;

    // FIXED (was the round<=8 bug): blockDim is 256, so strided loops are
    // required to cover all 400 / 288 elements. Previously spad[256..399]
    // (padding ring of channels 2-3) and w2s[256..287] (channel-7 weights)
    // were uninitialized smem garbage.
    for (int idx = tid; idx < 400; idx += 256) ((float*)spad)[idx] = 0.f;
    for (int idx = tid; idx < 288; idx += 256) w2s[idx] = w2[idx];

    int c1 = tid >> 6, y1 = (tid >> 3) & 7, x1 = tid & 7;
    float lw0 = 0.f, lw1 = 0.f;
    int c2 = 0, y2 = 0, x2 = 0;
    if (tid < 128) {
        lw0 = lin_w[tid];
        lw1 = lin_w[128 + tid];
        c2 = tid >> 4; y2 = (tid >> 2) & 3; x2 = tid & 3;
    }

    float v1m = 0.f, v1u = 0.f, v2m = 0.f, v2u = 0.f;
    const float* hp = g_h1 + (size_t)b * 100 * 256;
    float hn = hp[tid];                 // prefetch t=0
    __syncthreads();

    for (int t = 0; t < 100; t++) {
        float h = hn;
        if (t < 99) hn = hp[(t + 1) * 256 + tid];   // prefetch next step

        // layer-1 exp_leak membrane, then LIF (membrane-subtract reset)
        v1m = ALPHA * v1m + h;
        v1u = ALPHA * v1u + v1m;
        float s = (v1u >= 1.0f) ? 1.0f : 0.0f;
        v1u -= s;
        spad[c1][y1 + 1][x1 + 1] = s;
        __syncthreads();

        if (tid < 128) {
            // direct conv2(3x3,pad1): 2x2 conv pixels, then avgpool2 mean
            float csum = 0.f;
#pragma unroll
            for (int j = 0; j < 2; j++)
#pragma unroll
                for (int i = 0; i < 2; i++) {
                    float cp = 0.f;
#pragma unroll
                    for (int ic = 0; ic < 4; ic++)
#pragma unroll
                        for (int ky = 0; ky < 3; ky++)
#pragma unroll
                            for (int kx = 0; kx < 3; kx++)
                                cp = fmaf(w2s[((c2 * 4 + ic) * 3 + ky) * 3 + kx],
                                          spad[ic][2 * y2 + j + ky][2 * x2 + i + kx],
                                          cp);
                    csum += cp;
                }
            float acc = csum * 0.25f;

            // layer-2 exp_leak + LIF
            v2m = ALPHA * v2m + acc;
            v2u = ALPHA * v2u + v2m;
            float s2 = (v2u >= 1.0f) ? 1.0f : 0.0f;
            v2u -= s2;

            // linear: out[b,t,o] = sum_f lw[o,f] * s2[f]
            float p0 = s2 * lw0, p1 = s2 * lw1;
#pragma unroll
            for (int off = 16; off; off >>= 1) {
                p0 += __shfl_down_sync(0xffffffffu, p0, off);
                p1 += __shfl_down_sync(0xffffffffu, p1, off);
            }
            if ((tid & 31) == 0) {
                red[(tid >> 5) * 2] = p0;
                red[(tid >> 5) * 2 + 1] = p1;
            }
        }
        __syncthreads();
        if (tid < 2)
            out[(b * 100 + t) * 2 + tid] =
                red[tid] + red[tid + 2] + red[tid + 4] + red[tid + 6];
        // red(t+1) writes occur after the next iteration's first barrier,
        // ordering them after this read; spad(t+1) writes are ordered after
        // this iteration's conv reads by the barrier just above.
    }
}

// ---------------------------------------------------------------------------
extern "C" void kernel_launch(void* const* d_in, const int* in_sizes, int n_in,
                              void* d_out, int out_size) {
    // Rank-based input binding: invariant to metadata ordering AND units.
    //   x     : unique largest buffer
    //   w1    : smallest of the remaining three (200 elems)
    //   lin_w : middle                          (256 elems)
    //   w2    : largest of the small three      (288 elems)
    int xi = 0;
    for (int i = 1; i < n_in; i++)
        if (in_sizes[i] > in_sizes[xi]) xi = i;

    int rest[3]; int nr = 0;
    for (int i = 0; i < n_in && nr < 3; i++)
        if (i != xi) rest[nr++] = i;
    for (int a = 0; a < 2; a++)
        for (int bq = 0; bq < 2 - a; bq++)
            if (in_sizes[rest[bq]] > in_sizes[rest[bq + 1]]) {
                int tmp = rest[bq]; rest[bq] = rest[bq + 1]; rest[bq + 1] = tmp;
            }

    const float* x  = (const float*)d_in[xi];       // [128,100,2,32,32]
    const float* w1 = (const float*)d_in[rest[0]];  // [4,2,5,5]
    const float* lw = (const float*)d_in[rest[1]];  // [2,128]
    const float* w2 = (const float*)d_in[rest[2]];  // [8,4,3,3]
    float* out = (float*)d_out;                     // [128,100,2]

    k_stage1<<<12800, 256>>>(x, w1);
    k_scan<<<128, 256>>>(w2, lw, out);
}

// round 11
// speedup vs baseline: 1.4537x; 1.4537x over previous
#include <cuda_runtime.h>
#include <cstdint>

#define ALPHA 0.9048374180359595f   // exp(-1/10), rounds to same f32 as JAX
#define BT 12800                     // B*T = 128*100

// Layer-1 pooled conv output, layout [sample = b*100+t][256 = c*64+y*8+x]
__device__ float g_h1[BT * 256];
// conv1(5x5,pad2)+pool4 folded to 8x8 stride-4, packed float4 over out-channels:
//   g_weff1q[(ic*8+dy)*8+dx] = {c0,c1,c2,c3}   (x1/16 folded in)
__device__ float4 g_weff1q[128];
// conv2(3x3,pad1)+pool2 folded to 4x4 stride-2, transposed [tap][c]:
//   g_weff2[(ic*16+dy*4+dx)*8 + c]             (x1/4 folded in)
__device__ float g_weff2[512];

// ---------------------------------------------------------------------------
// Precompute folded conv+pool kernels (tiny, idempotent)
// ---------------------------------------------------------------------------
__global__ void k_prep(const float* __restrict__ w1, const float* __restrict__ w2) {
    int i = threadIdx.x;                 // 0..511
    // Weff1: pooled tap d covers conv taps ky = d-j, j in [0,3]
    {
        int dx = i & 7, dy = (i >> 3) & 7, ic = (i >> 6) & 1, c = i >> 7;
        int iy0 = dy > 3 ? dy - 3 : 0, iy1 = dy < 4 ? dy : 4;
        int ix0 = dx > 3 ? dx - 3 : 0, ix1 = dx < 4 ? dx : 4;
        float s = 0.f;
        for (int iy = iy0; iy <= iy1; iy++)
            for (int ix = ix0; ix <= ix1; ix++)
                s += w1[((c * 2 + ic) * 5 + iy) * 5 + ix];
        ((float*)g_weff1q)[((ic * 8 + dy) * 8 + dx) * 4 + c] = s * (1.0f / 16.0f);
    }
    // Weff2
    {
        int dx = i & 3, dy = (i >> 2) & 3, ic = (i >> 4) & 3, c = i >> 6;
        int iy0 = dy > 1 ? dy - 1 : 0, iy1 = dy < 2 ? dy : 2;
        int ix0 = dx > 1 ? dx - 1 : 0, ix1 = dx < 2 ? dx : 2;
        float s = 0.f;
        for (int iy = iy0; iy <= iy1; iy++)
            for (int ix = ix0; ix <= ix1; ix++)
                s += w2[((c * 4 + ic) * 3 + iy) * 3 + ix];
        g_weff2[(ic * 16 + dy * 4 + dx) * 8 + c] = s * 0.25f;
    }
}

// ---------------------------------------------------------------------------
// Stage 1: folded conv1+pool4 as 8x8 stride-4 conv. 4 samples per block,
// 256 threads: thread = (sl = tid>>6, pos = tid&63 -> (py,px)), computes all
// 4 output channels (weights = one uniform float4 broadcast per tap).
// smem (q,r)-split layout: xs[sl][ic][r][row][q'] holds x col 4(q'-1)+r at
// padded row (y+2); stride-4 compute reads are bank-conflict-free.
// ---------------------------------------------------------------------------
__global__ void __launch_bounds__(256) k_stage1(const float* __restrict__ x) {
    __shared__ float xs[4][2][4][36][10];   // 11520 floats = 46 KB
    __shared__ float4 wq[128];
    int tid = threadIdx.x;

    float* xsf = (float*)xs;
    for (int idx = tid; idx < 11520; idx += 256) xsf[idx] = 0.f;
    if (tid < 128) wq[tid] = g_weff1q[tid];
    __syncthreads();

    // load 4 samples (8192 floats) coalesced; scatter conflict-free
    const float* xg = x + (size_t)blockIdx.x * 8192;
#pragma unroll
    for (int k = 0; k < 32; k++) {
        int idx = tid + k * 256;
        int sl = idx >> 11, rem = idx & 2047;
        int ic = rem >> 10, yy = (rem >> 5) & 31, cc = rem & 31;
        xs[sl][ic][cc & 3][yy + 2][(cc >> 2) + 1] = xg[idx];
    }
    __syncthreads();

    int sl = tid >> 6, pos = tid & 63, py = pos >> 3, px = pos & 7;
    float a0 = 0.f, a1 = 0.f, a2 = 0.f, a3 = 0.f;
#pragma unroll
    for (int ic = 0; ic < 2; ic++)
#pragma unroll
        for (int dy = 0; dy < 8; dy++) {
            int row = 4 * py + dy;
#pragma unroll
            for (int dx = 0; dx < 8; dx++) {
                int u = 4 * px + dx + 2;              // col+4 encoding
                float xv = xs[sl][ic][u & 3][row][u >> 2];
                float4 w = wq[(ic * 8 + dy) * 8 + dx];  // uniform LDS.128 bcast
                a0 = fmaf(xv, w.x, a0);
                a1 = fmaf(xv, w.y, a1);
                a2 = fmaf(xv, w.z, a2);
                a3 = fmaf(xv, w.w, a3);
            }
        }
    size_t s = (size_t)blockIdx.x * 4 + sl;
    g_h1[s * 256 +   0 + pos] = a0;
    g_h1[s * 256 +  64 + pos] = a1;
    g_h1[s * 256 + 128 + pos] = a2;
    g_h1[s * 256 + 192 + pos] = a3;
}

// ---------------------------------------------------------------------------
// Stages 2-5 fused: per-batch temporal scan (block = one b, 256 threads).
//   layer-1 exp_leak+LIF (256 lanes) -> spike pad (double-buffered, 1 barrier
//   per step) -> folded conv2 4x4 stride-2 (128 lanes) -> layer-2 exp_leak+LIF
//   -> spikes captured as ballot bitmasks; linear [2,128] deferred post-loop.
// ---------------------------------------------------------------------------
__global__ void __launch_bounds__(256) k_scan(const float* __restrict__ lin_w,
                                              float* __restrict__ out) {
    __shared__ float spad[2][4][10][10];   // double-buffered, borders stay 0
    __shared__ float wf2[512];             // [tap][c2] transposed
    __shared__ float lws2[256];            // interleaved [f][o]
    __shared__ uint32_t sbits[100][4];     // layer-2 spike masks per step
    int tid = threadIdx.x;
    int b = blockIdx.x;

    for (int idx = tid; idx < 800; idx += 256) ((float*)spad)[idx] = 0.f;
    for (int idx = tid; idx < 512; idx += 256) wf2[idx] = g_weff2[idx];
    lws2[tid] = lin_w[(tid & 1) * 128 + (tid >> 1)];   // lws2[f*2+o]

    int c1 = tid >> 6, y1 = (tid >> 3) & 7, x1 = tid & 7;
    int c2 = tid >> 4, y2 = (tid >> 2) & 3, x2 = tid & 3;   // valid for tid<128
    int lane = tid & 31, warp = tid >> 5;

    float v1m = 0.f, v1u = 0.f, v2m = 0.f, v2u = 0.f;
    const float* hp = g_h1 + (size_t)b * 100 * 256;
    float hcur = hp[tid];
    float hnext = hp[256 + tid];
    __syncthreads();

    for (int t = 0; t < 100; t++) {
        float h = hcur;
        hcur = hnext;
        if (t < 98) hnext = hp[(t + 2) * 256 + tid];   // depth-2 prefetch

        // layer-1 exp_leak membrane, then LIF (membrane-subtract reset)
        v1m = ALPHA * v1m + h;
        v1u = ALPHA * v1u + v1m;
        float s = (v1u >= 1.0f) ? 1.0f : 0.0f;
        v1u -= s;
        int p = t & 1;
        spad[p][c1][y1 + 1][x1 + 1] = s;
        __syncthreads();   // single barrier: double-buffer removes WAR hazard

        if (tid < 128) {
            // folded conv2+pool2: 4x4 stride-2 window over spike pad
            float a0 = 0.f, a1 = 0.f, a2 = 0.f, a3 = 0.f;
#pragma unroll
            for (int dy = 0; dy < 4; dy++)
#pragma unroll
                for (int dx = 0; dx < 4; dx++) {
                    int tp = dy * 4 + dx;
                    a0 = fmaf(wf2[(0 + tp) * 8 + c2],  spad[p][0][2*y2+dy][2*x2+dx], a0);
                    a1 = fmaf(wf2[(16 + tp) * 8 + c2], spad[p][1][2*y2+dy][2*x2+dx], a1);
                    a2 = fmaf(wf2[(32 + tp) * 8 + c2], spad[p][2][2*y2+dy][2*x2+dx], a2);
                    a3 = fmaf(wf2[(48 + tp) * 8 + c2], spad[p][3][2*y2+dy][2*x2+dx], a3);
                }
            float acc = (a0 + a1) + (a2 + a3);

            // layer-2 exp_leak + LIF
            v2m = ALPHA * v2m + acc;
            v2u = ALPHA * v2u + v2m;
            bool sp = (v2u >= 1.0f);
            v2u -= sp ? 1.0f : 0.0f;

            uint32_t m = __ballot_sync(0xffffffffu, sp);  // warps 0-3 full
            if (lane == 0) sbits[t][warp] = m;
        }
    }
    __syncthreads();

    // Deferred linear: out[b,t,o] = sum_f lw[o,f] * spike[t,f]
    if (tid < 200) {
        int t = tid >> 1, o = tid & 1;
        float acc = 0.f;
#pragma unroll
        for (int w = 0; w < 4; w++) {
            uint32_t m = sbits[t][w];
#pragma unroll
            for (int j = 0; j < 32; j++)
                acc += (m >> j & 1u) ? lws2[(w * 32 + j) * 2 + o] : 0.f;
        }
        out[(b * 100 + t) * 2 + o] = acc;
    }
}

// ---------------------------------------------------------------------------
extern "C" void kernel_launch(void* const* d_in, const int* in_sizes, int n_in,
                              void* d_out, int out_size) {
    // Rank-based input binding: invariant to metadata ordering AND units.
    int xi = 0;
    for (int i = 1; i < n_in; i++)
        if (in_sizes[i] > in_sizes[xi]) xi = i;

    int rest[3]; int nr = 0;
    for (int i = 0; i < n_in && nr < 3; i++)
        if (i != xi) rest[nr++] = i;
    for (int a = 0; a < 2; a++)
        for (int bq = 0; bq < 2 - a; bq++)
            if (in_sizes[rest[bq]] > in_sizes[rest[bq + 1]]) {
                int tmp = rest[bq]; rest[bq] = rest[bq + 1]; rest[bq + 1] = tmp;
            }

    const float* x  = (const float*)d_in[xi];       // [128,100,2,32,32]
    const float* w1 = (const float*)d_in[rest[0]];  // [4,2,5,5]   (200)
    const float* lw = (const float*)d_in[rest[1]];  // [2,128]     (256)
    const float* w2 = (const float*)d_in[rest[2]];  // [8,4,3,3]   (288)
    float* out = (float*)d_out;                     // [128,100,2]

    k_prep<<<1, 512>>>(w1, w2);
    k_stage1<<<3200, 256>>>(x);
    k_scan<<<128, 256>>>(lw, out);
}